// round 12
// baseline (speedup 1.0000x reference)
#include <cuda_runtime.h>
#include <cuda_fp16.h>
#include <cstdint>

// ---------------- problem constants ----------------
#define N_NODES 8192
#define F_IN    256
#define D_OUT   64
#define LOG2E   1.4426950408889634f

// ---------------- device scratch (no allocation allowed) ----------------
__device__ float g_h[N_NODES * D_OUT];
__device__ float g_e1[N_NODES];
__device__ float g_e2[N_NODES];
// H in mma.m16n8k16 B-fragment order, paired: [jb = j/16][n8pair = d/16][lane]
// uint4 = {frag(n8=2p).x, frag(n8=2p).y, frag(n8=2p+1).x, frag(n8=2p+1).y}
// frag(n8).x = f16x2(Ht[n][k0], Ht[n][k0+1]), .y = f16x2(Ht[n][k0+8], Ht[n][k0+9])
// n = n8*8 + (lane>>2), k0 = 2*(lane&3), j = jb*16 + k.
__device__ uint4 g_hf2[(N_NODES / 16) * 4 * 32];

// ---------------- helpers ----------------
__device__ __forceinline__ uint32_t smem_u32(const void* p) {
    uint32_t a;
    asm("{ .reg .u64 t; cvta.to.shared.u64 t, %1; cvt.u32.u64 %0, t; }"
        : "=r"(a) : "l"(p));
    return a;
}
__device__ __forceinline__ uint32_t pack_f16x2(float lo, float hi) {
    uint32_t r;
    asm("cvt.rn.f16x2.f32 %0, %1, %2;" : "=r"(r) : "f"(hi), "f"(lo));
    return r;
}
__device__ __forceinline__ float ex2(float x) {
    float r;
    asm("ex2.approx.ftz.f32 %0, %1;" : "=f"(r) : "f"(x));
    return r;
}
__device__ __forceinline__ unsigned long long pk2(float lo, float hi) {
    unsigned long long r;
    asm("mov.b64 %0, {%1, %2};" : "=l"(r) : "f"(lo), "f"(hi));
    return r;
}
__device__ __forceinline__ void upk2(float& lo, float& hi, unsigned long long v) {
    asm("mov.b64 {%0, %1}, %2;" : "=f"(lo), "=f"(hi) : "l"(v));
}
__device__ __forceinline__ void add2(unsigned long long& d, unsigned long long a) {
    asm("add.rn.f32x2 %0, %0, %1;" : "+l"(d) : "l"(a));
}
__device__ __forceinline__ void ldsm_x4(uint32_t (&r)[4], uint32_t addr) {
    asm volatile("ldmatrix.sync.aligned.m8n8.x4.shared.b16 {%0,%1,%2,%3}, [%4];"
                 : "=r"(r[0]), "=r"(r[1]), "=r"(r[2]), "=r"(r[3]) : "r"(addr));
}
__device__ __forceinline__ void mma16816(float (&c)[4], const uint32_t (&a)[4],
                                         const uint32_t* b) {
    asm volatile("mma.sync.aligned.m16n8k16.row.col.f32.f16.f16.f32 "
        "{%0,%1,%2,%3}, {%4,%5,%6,%7}, {%8,%9}, {%0,%1,%2,%3};"
        : "+f"(c[0]), "+f"(c[1]), "+f"(c[2]), "+f"(c[3])
        : "r"(a[0]), "r"(a[1]), "r"(a[2]), "r"(a[3]), "r"(b[0]), "r"(b[1]));
}

// ---------------- kernel 1: h = x @ trans, paired fragment output ----------------
__global__ void k_h_gemm(const float* __restrict__ x,
                         const float* __restrict__ trans) {
    __shared__ float xs[16 * F_IN];
    __shared__ float ts[64 * D_OUT];
    __shared__ float trs[64 * 17];

    const int t = threadIdx.x;
    const int d = t & 63;
    const int rg = t >> 6;
    const int ibase = blockIdx.x * 16;

    {
        const float4* xg4 = reinterpret_cast<const float4*>(x) + (size_t)ibase * (F_IN / 4);
        float4* xs4 = reinterpret_cast<float4*>(xs);
        #pragma unroll
        for (int q = 0; q < 4; q++) xs4[t + q * 256] = xg4[t + q * 256];
    }

    float acc[4] = {0.f, 0.f, 0.f, 0.f};

    for (int kc = 0; kc < 4; kc++) {
        {
            const float4* tg4 = reinterpret_cast<const float4*>(trans) + kc * 1024;
            float4* ts4 = reinterpret_cast<float4*>(ts);
            #pragma unroll
            for (int q = 0; q < 4; q++) ts4[t + q * 256] = tg4[t + q * 256];
        }
        __syncthreads();
        #pragma unroll 4
        for (int k4 = 0; k4 < 16; k4++) {
            float4 xv[4];
            #pragma unroll
            for (int r = 0; r < 4; r++)
                xv[r] = *reinterpret_cast<const float4*>(
                    &xs[(rg * 4 + r) * F_IN + kc * 64 + k4 * 4]);
            #pragma unroll
            for (int kk = 0; kk < 4; kk++) {
                const float tv = ts[(k4 * 4 + kk) * 64 + d];
                #pragma unroll
                for (int r = 0; r < 4; r++)
                    acc[r] = fmaf(reinterpret_cast<const float*>(&xv[r])[kk],
                                  tv, acc[r]);
            }
        }
        __syncthreads();
    }

    #pragma unroll
    for (int r = 0; r < 4; r++) {
        g_h[(size_t)(ibase + rg * 4 + r) * D_OUT + d] = acc[r];
        trs[d * 17 + rg * 4 + r] = acc[r];
    }
    __syncthreads();

    // write paired B fragments for jb = blockIdx.x
    {
        const int l = t & 31;
        const int n8b = t >> 5;                     // 0..7
        const int n = n8b * 8 + (l >> 2);
        const int k0 = (l & 3) * 2;
        const float* r = trs + n * 17;
        uint2 v;
        v.x = pack_f16x2(r[k0], r[k0 + 1]);
        v.y = pack_f16x2(r[k0 + 8], r[k0 + 9]);
        uint2* g2 = reinterpret_cast<uint2*>(g_hf2);
        g2[((((size_t)blockIdx.x * 4 + (n8b >> 1)) * 32 + l) << 1) | (n8b & 1)] = v;
    }
}

// ---------------- kernel 2: e1/e2 projections ----------------
__global__ void k_e(const float* __restrict__ attn) {
    const int wid = threadIdx.x >> 5;
    const int lane = threadIdx.x & 31;
    const int row = blockIdx.x * 8 + wid;

    const float h0 = g_h[(size_t)row * D_OUT + lane];
    const float h1 = g_h[(size_t)row * D_OUT + lane + 32];
    float v1 = h0 * attn[lane] + h1 * attn[lane + 32];
    float v2 = h0 * attn[64 + lane] + h1 * attn[96 + lane];
    #pragma unroll
    for (int o = 16; o > 0; o >>= 1) {
        v1 += __shfl_xor_sync(0xffffffffu, v1, o);
        v2 += __shfl_xor_sync(0xffffffffu, v2, o);
    }
    if (lane == 0) { g_e1[row] = v1; g_e2[row] = v2; }
}

// ---------------- kernel 3: warp-specialized attention, K-split consumers ----------------
// CTA: 32 rows x full 8192 j. Tile: 32 rows x 64 j. 128 tiles. 256 CTAs, 2/SM.
#define ROWS 32
#define PROW 144
#define PHI0 0
#define PHI1 4608
#define RED_OFF 9216                 // 6 x 4KB k-partial regions
#define SMEM_BYTES (9216 + 24576 + 128)

#define NTILES 128

__global__ __launch_bounds__(512, 2)
void k_attn_ws(const int* __restrict__ mask,
               const float* __restrict__ e2g,
               float* __restrict__ out) {
    extern __shared__ char dsmem[];
    __shared__ float zs[ROWS];

    const int t = threadIdx.x;
    const int lane = t & 31;
    const int w = t >> 5;
    const int ibase = blockIdx.x * ROWS;

    const uint32_t sbase = smem_u32(dsmem);
    const uint32_t abase = (sbase + 127) & ~127u;
    char* ab = dsmem + (abase - sbase);

    // ============ producer state (warps 0-7, t < 256) ============
    const int prow = t >> 3;            // row within block (0..31)
    const int j0 = (t & 7) << 3;        // 8 j per thread
    const float ei8 = g_e1[ibase + prow] * LOG2E - 8.0f;

    const uint4* mrow_p = reinterpret_cast<const uint4*>(
        mask + (size_t)(ibase + prow) * N_NODES + j0);   // tile stride: 16 uint4

    uint4 mreg[2];
    unsigned long long zacc = 0ull;

    // ============ consumer state (warps 8-15) ============
    const int wc = w - 8;
    const int mgrp = wc & 1;            // m-group (16 rows)
    const int kk = wc >> 1;             // k-quarter (16 j of the 64-j tile)
    const uint32_t a_base = (uint32_t)(
        (mgrp * 16 + (lane & 15)) * PROW + ((lane >> 4) << 4) + kk * 32);
    const uint4* bgp = g_hf2 + (size_t)kk * 4 * 32 + lane;   // + jbtile*16*... below

    uint4 bf[4];
    float acc[8][4];
    #pragma unroll
    for (int n8 = 0; n8 < 8; n8++)
        #pragma unroll
        for (int c = 0; c < 4; c++) acc[n8][c] = 0.f;

    // prologue
    if (w < 8) {
        mreg[0] = mrow_p[0];
        mreg[1] = mrow_p[1];
    } else {
        // prefetch B for tile 0: jb = 0*4 + kk
        #pragma unroll
        for (int p = 0; p < 4; p++) bf[p] = __ldg(bgp + p * 32);
    }

    for (int it = 0; it <= NTILES; it++) {
        __syncthreads();
        if (w < 8) {
            if (it < NTILES) {
                const int buf = it & 1;
                const uint32_t phioff = buf ? PHI1 : PHI0;
                // compute P (8 elems), single fp16, folded 2^-8 scale
                const float4* e2p = reinterpret_cast<const float4*>(
                    e2g + it * 64 + j0);
                uint32_t hiu[4];
                #pragma unroll
                for (int g = 0; g < 2; g++) {
                    const float4 ev = __ldg(e2p + g);
                    const uint4 mm = mreg[g];
                    const float e4[4] = {ev.x, ev.y, ev.z, ev.w};
                    const uint32_t m4[4] = {mm.x, mm.y, mm.z, mm.w};
                    float p[4];
                    #pragma unroll
                    for (int k = 0; k < 4; k++) {
                        const float a = fmaf(e4[k], LOG2E, ei8);
                        const float b = fmaf(a, 0.2f, -6.4f);
                        const float pe = ex2(fmaxf(a, b));
                        p[k] = __uint_as_float(m4[k] * __float_as_uint(pe));
                    }
                    add2(zacc, pk2(p[0], p[1]));
                    add2(zacc, pk2(p[2], p[3]));
                    hiu[g * 2]     = pack_f16x2(p[0], p[1]);
                    hiu[g * 2 + 1] = pack_f16x2(p[2], p[3]);
                }
                *reinterpret_cast<uint4*>(ab + phioff + prow * PROW + j0 * 2) =
                    make_uint4(hiu[0], hiu[1], hiu[2], hiu[3]);
                // prefetch next mask tile (wrap keeps addresses valid)
                {
                    const int nt = (it + 1 < NTILES) ? it + 1 : 0;
                    const uint4* mp = mrow_p + nt * 16;
                    mreg[0] = mp[0];
                    mreg[1] = mp[1];
                }
            }
        } else {
            if (it >= 1) {
                const int buf = (it - 1) & 1;
                const uint32_t phi = abase + (buf ? PHI1 : PHI0);
                uint32_t ah[4];
                ldsm_x4(ah, phi + a_base);
                #pragma unroll
                for (int p = 0; p < 4; p++) {
                    mma16816(acc[2 * p],     ah, &bf[p].x);
                    mma16816(acc[2 * p + 1], ah, &bf[p].z);
                }
                // prefetch B for tile `it` (consumed next phase; wrap at end)
                {
                    const int nt = (it < NTILES) ? it : 0;
                    const uint4* bp = bgp + (size_t)nt * 16 * 32;  // nt*4 jb units
                    #pragma unroll
                    for (int p = 0; p < 4; p++) bf[p] = __ldg(bp + p * 32);
                }
            }
        }
    }

    // ---- epilogue ----
    if (w < 8) {
        float zlo, zhi;
        upk2(zlo, zhi, zacc);
        float zsum = zlo + zhi;
        zsum += __shfl_xor_sync(0xffffffffu, zsum, 1);
        zsum += __shfl_xor_sync(0xffffffffu, zsum, 2);
        zsum += __shfl_xor_sync(0xffffffffu, zsum, 4);
        if ((t & 7) == 0) zs[prow] = zsum;
    } else if (kk > 0) {
        // store k-partials to smem region [(kk-1)*2 + mgrp]
        float* rg = reinterpret_cast<float*>(
            ab + RED_OFF + ((kk - 1) * 2 + mgrp) * 4096);
        const int r0 = lane >> 2;
        const int c0 = (lane & 3) * 2;
        #pragma unroll
        for (int n8 = 0; n8 < 8; n8++) {
            *reinterpret_cast<float2*>(&rg[r0 * 64 + n8 * 8 + c0]) =
                make_float2(acc[n8][0], acc[n8][1]);
            *reinterpret_cast<float2*>(&rg[(r0 + 8) * 64 + n8 * 8 + c0]) =
                make_float2(acc[n8][2], acc[n8][3]);
        }
    }
    __syncthreads();
    if (w >= 8 && kk == 0) {
        const int r0 = lane >> 2;
        const int c0 = (lane & 3) * 2;
        // add the 3 k-partials
        #pragma unroll
        for (int q = 0; q < 3; q++) {
            const float* rg = reinterpret_cast<const float*>(
                ab + RED_OFF + (q * 2 + mgrp) * 4096);
            #pragma unroll
            for (int n8 = 0; n8 < 8; n8++) {
                const float2 v0 = *reinterpret_cast<const float2*>(
                    &rg[r0 * 64 + n8 * 8 + c0]);
                const float2 v1 = *reinterpret_cast<const float2*>(
                    &rg[(r0 + 8) * 64 + n8 * 8 + c0]);
                acc[n8][0] += v0.x; acc[n8][1] += v0.y;
                acc[n8][2] += v1.x; acc[n8][3] += v1.y;
            }
        }
        const int row0 = mgrp * 16 + r0;
        const float rz0 = 1.0f / zs[row0];
        const float rz1 = 1.0f / zs[row0 + 8];
        #pragma unroll
        for (int n8 = 0; n8 < 8; n8++) {
            const int col = n8 * 8 + c0;
            *reinterpret_cast<float2*>(
                out + (size_t)(ibase + row0) * D_OUT + col) =
                make_float2(acc[n8][0] * rz0, acc[n8][1] * rz0);
            *reinterpret_cast<float2*>(
                out + (size_t)(ibase + row0 + 8) * D_OUT + col) =
                make_float2(acc[n8][2] * rz1, acc[n8][3] * rz1);
        }
    }
}

// ---------------- launch ----------------
extern "C" void kernel_launch(void* const* d_in, const int* in_sizes, int n_in,
                              void* d_out, int out_size) {
    const float* x     = (const float*)d_in[0];   // [8192, 256]
    const int*   mask  = (const int*)d_in[1];     // [8192, 8192]
    const float* trans = (const float*)d_in[2];   // [256, 64]
    const float* attn  = (const float*)d_in[3];   // [128, 1]
    float* out = (float*)d_out;                   // [8192, 64]

    cudaFuncSetAttribute(k_attn_ws, cudaFuncAttributeMaxDynamicSharedMemorySize,
                         SMEM_BYTES);

    k_h_gemm<<<N_NODES / 16, 256>>>(x, trans);
    k_e<<<N_NODES / 8, 256>>>(attn);

    float* e2g;
    cudaGetSymbolAddress((void**)&e2g, g_e2);
    k_attn_ws<<<N_NODES / ROWS, 512, SMEM_BYTES>>>(mask, e2g, out);
}

// round 13
// speedup vs baseline: 1.9314x; 1.9314x over previous
#include <cuda_runtime.h>
#include <cuda_fp16.h>
#include <cstdint>

// ---------------- problem constants ----------------
#define N_NODES 8192
#define F_IN    256
#define D_OUT   64
#define LOG2E   1.4426950408889634f

// ---------------- device scratch (no allocation allowed) ----------------
__device__ float g_h[N_NODES * D_OUT];
__device__ float g_e1[N_NODES];
__device__ float g_e2[N_NODES];
// H in mma.m16n8k16 B-fragment order: [jb = j/16][n8b = d/8][lane]
// uint2 = {f16x2(Ht[n][k0],Ht[n][k0+1]), f16x2(Ht[n][k0+8],Ht[n][k0+9])},
// n = n8b*8 + (lane>>2), k0 = 2*(lane&3), j = jb*16 + k.
__device__ uint2 g_hf[(N_NODES / 16) * 8 * 32];

// ---------------- helpers ----------------
__device__ __forceinline__ uint32_t smem_u32(const void* p) {
    uint32_t a;
    asm("{ .reg .u64 t; cvta.to.shared.u64 t, %1; cvt.u32.u64 %0, t; }"
        : "=r"(a) : "l"(p));
    return a;
}
__device__ __forceinline__ uint32_t pack_f16x2(float lo, float hi) {
    uint32_t r;
    asm("cvt.rn.f16x2.f32 %0, %1, %2;" : "=r"(r) : "f"(hi), "f"(lo));
    return r;
}
__device__ __forceinline__ float ex2(float x) {
    float r;
    asm("ex2.approx.ftz.f32 %0, %1;" : "=f"(r) : "f"(x));
    return r;
}
__device__ __forceinline__ unsigned long long pk2(float lo, float hi) {
    unsigned long long r;
    asm("mov.b64 %0, {%1, %2};" : "=l"(r) : "f"(lo), "f"(hi));
    return r;
}
__device__ __forceinline__ void upk2(float& lo, float& hi, unsigned long long v) {
    asm("mov.b64 {%0, %1}, %2;" : "=f"(lo), "=f"(hi) : "l"(v));
}
__device__ __forceinline__ void add2(unsigned long long& d, unsigned long long a) {
    asm("add.rn.f32x2 %0, %0, %1;" : "+l"(d) : "l"(a));
}
__device__ __forceinline__ void ldsm_x4(uint32_t (&r)[4], uint32_t addr) {
    asm volatile("ldmatrix.sync.aligned.m8n8.x4.shared.b16 {%0,%1,%2,%3}, [%4];"
                 : "=r"(r[0]), "=r"(r[1]), "=r"(r[2]), "=r"(r[3]) : "r"(addr));
}
__device__ __forceinline__ void mma16816(float (&c)[4], const uint32_t (&a)[4],
                                         const uint32_t* b) {
    asm volatile("mma.sync.aligned.m16n8k16.row.col.f32.f16.f16.f32 "
        "{%0,%1,%2,%3}, {%4,%5,%6,%7}, {%8,%9}, {%0,%1,%2,%3};"
        : "+f"(c[0]), "+f"(c[1]), "+f"(c[2]), "+f"(c[3])
        : "r"(a[0]), "r"(a[1]), "r"(a[2]), "r"(a[3]), "r"(b[0]), "r"(b[1]));
}

// ---------------- kernel 1: h = x @ trans, fragment-order H output ----------------
__global__ void k_h_gemm(const float* __restrict__ x,
                         const float* __restrict__ trans) {
    __shared__ float xs[16 * F_IN];
    __shared__ float ts[64 * D_OUT];
    __shared__ float trs[64 * 17];

    const int t = threadIdx.x;
    const int d = t & 63;
    const int rg = t >> 6;
    const int ibase = blockIdx.x * 16;

    {
        const float4* xg4 = reinterpret_cast<const float4*>(x) + (size_t)ibase * (F_IN / 4);
        float4* xs4 = reinterpret_cast<float4*>(xs);
        #pragma unroll
        for (int q = 0; q < 4; q++) xs4[t + q * 256] = xg4[t + q * 256];
    }

    float acc[4] = {0.f, 0.f, 0.f, 0.f};

    for (int kc = 0; kc < 4; kc++) {
        {
            const float4* tg4 = reinterpret_cast<const float4*>(trans) + kc * 1024;
            float4* ts4 = reinterpret_cast<float4*>(ts);
            #pragma unroll
            for (int q = 0; q < 4; q++) ts4[t + q * 256] = tg4[t + q * 256];
        }
        __syncthreads();
        #pragma unroll 4
        for (int k4 = 0; k4 < 16; k4++) {
            float4 xv[4];
            #pragma unroll
            for (int r = 0; r < 4; r++)
                xv[r] = *reinterpret_cast<const float4*>(
                    &xs[(rg * 4 + r) * F_IN + kc * 64 + k4 * 4]);
            #pragma unroll
            for (int kk = 0; kk < 4; kk++) {
                const float tv = ts[(k4 * 4 + kk) * 64 + d];
                #pragma unroll
                for (int r = 0; r < 4; r++)
                    acc[r] = fmaf(reinterpret_cast<const float*>(&xv[r])[kk],
                                  tv, acc[r]);
            }
        }
        __syncthreads();
    }

    #pragma unroll
    for (int r = 0; r < 4; r++) {
        g_h[(size_t)(ibase + rg * 4 + r) * D_OUT + d] = acc[r];
        trs[d * 17 + rg * 4 + r] = acc[r];
    }
    __syncthreads();

    // write B fragments for jb = blockIdx.x (16 j-rows)
    {
        const int l = t & 31;
        const int n8b = t >> 5;                     // 0..7
        const int n = n8b * 8 + (l >> 2);
        const int k0 = (l & 3) * 2;
        const float* r = trs + n * 17;
        uint2 v;
        v.x = pack_f16x2(r[k0], r[k0 + 1]);
        v.y = pack_f16x2(r[k0 + 8], r[k0 + 9]);
        g_hf[((size_t)blockIdx.x * 8 + n8b) * 32 + l] = v;
    }
}

// ---------------- kernel 2: e1/e2 projections ----------------
__global__ void k_e(const float* __restrict__ attn) {
    const int wid = threadIdx.x >> 5;
    const int lane = threadIdx.x & 31;
    const int row = blockIdx.x * 8 + wid;

    const float h0 = g_h[(size_t)row * D_OUT + lane];
    const float h1 = g_h[(size_t)row * D_OUT + lane + 32];
    float v1 = h0 * attn[lane] + h1 * attn[lane + 32];
    float v2 = h0 * attn[64 + lane] + h1 * attn[96 + lane];
    #pragma unroll
    for (int o = 16; o > 0; o >>= 1) {
        v1 += __shfl_xor_sync(0xffffffffu, v1, o);
        v2 += __shfl_xor_sync(0xffffffffu, v2, o);
    }
    if (lane == 0) { g_e1[row] = v1; g_e2[row] = v2; }
}

// ---------------- kernel 3: warp-specialized attention ----------------
// CTA: 32 rows x full 8192 j. Tile: 32 rows x 64 j. 128 tiles. 256 CTAs, 2/SM.
// P tile via smem (double buffer); B fragments via direct coalesced LDG
// (single register buffer, prefetched one phase ahead).
#define ROWS 32
#define PROW 144
#define PHI0 0
#define PHI1 4608
#define SMEM_BYTES (9216 + 128)

#define NTILES 128

__global__ __launch_bounds__(512, 2)
void k_attn_ws(const int* __restrict__ mask,
               const float* __restrict__ e2g,
               float* __restrict__ out) {
    extern __shared__ char dsmem[];
    __shared__ float zs[ROWS];

    const int t = threadIdx.x;
    const int lane = t & 31;
    const int w = t >> 5;
    const int ibase = blockIdx.x * ROWS;

    const uint32_t sbase = smem_u32(dsmem);
    const uint32_t abase = (sbase + 127) & ~127u;
    char* ab = dsmem + (abase - sbase);

    // ============ producer state (warps 0-7, t < 256) ============
    const int prow = t >> 3;            // row within block (0..31)
    const int j0 = (t & 7) << 3;        // 8 j per thread
    const float ei8 = g_e1[ibase + prow] * LOG2E - 8.0f;

    const uint4* mrow_p = reinterpret_cast<const uint4*>(
        mask + (size_t)(ibase + prow) * N_NODES + j0);   // tile stride: 16 uint4

    uint4 mreg[2];
    unsigned long long zacc = 0ull;

    // ============ consumer state (warps 8-15) ============
    const int wc = w - 8;
    const int mgrp = wc & 1;            // m-group (16 rows)
    const int ngrp = wc >> 1;           // n-group (16 cols = 2 n8 frags)
    const uint32_t a_base = (uint32_t)(
        (mgrp * 16 + (lane & 15)) * PROW + ((lane >> 4) << 4));
    // B fragment pointer: jb-unit stride 8*32 uint2; tile it -> jb = it*4 + kk
    const uint2* bgp = g_hf + (size_t)(ngrp * 2) * 32 + lane;

    uint2 bf[8];                        // [kk*2 + p], single buffer (16 regs)
    float acc[2][4];
    #pragma unroll
    for (int nf = 0; nf < 2; nf++)
        #pragma unroll
        for (int c = 0; c < 4; c++) acc[nf][c] = 0.f;

    // prologue
    if (w < 8) {
        mreg[0] = mrow_p[0];
        mreg[1] = mrow_p[1];
    } else {
        // prefetch B fragments for tile 0: jb = kk (kk = 0..3)
        #pragma unroll
        for (int kk = 0; kk < 4; kk++) {
            const uint2* bp = bgp + (size_t)kk * 256;   // kk jb-units of 8*32
            bf[kk * 2]     = __ldg(bp);
            bf[kk * 2 + 1] = __ldg(bp + 32);
        }
    }

    for (int it = 0; it <= NTILES; it++) {
        __syncthreads();
        if (w < 8) {
            if (it < NTILES) {
                const uint32_t phioff = (it & 1) ? PHI1 : PHI0;
                const float4* e2p = reinterpret_cast<const float4*>(
                    e2g + it * 64 + j0);
                uint32_t hiu[4];
                #pragma unroll
                for (int g = 0; g < 2; g++) {
                    const float4 ev = __ldg(e2p + g);
                    const uint4 mm = mreg[g];
                    const float e4[4] = {ev.x, ev.y, ev.z, ev.w};
                    const uint32_t m4[4] = {mm.x, mm.y, mm.z, mm.w};
                    float p[4];
                    #pragma unroll
                    for (int k = 0; k < 4; k++) {
                        const float a = fmaf(e4[k], LOG2E, ei8);
                        const float b = fmaf(a, 0.2f, -6.4f);
                        const float pe = ex2(fmaxf(a, b));
                        p[k] = __uint_as_float(m4[k] * __float_as_uint(pe));
                    }
                    add2(zacc, pk2(p[0], p[1]));
                    add2(zacc, pk2(p[2], p[3]));
                    hiu[g * 2]     = pack_f16x2(p[0], p[1]);
                    hiu[g * 2 + 1] = pack_f16x2(p[2], p[3]);
                }
                *reinterpret_cast<uint4*>(ab + phioff + prow * PROW + j0 * 2) =
                    make_uint4(hiu[0], hiu[1], hiu[2], hiu[3]);
                // prefetch next mask tile (wrap keeps addresses valid)
                {
                    const int nt = (it + 1 < NTILES) ? it + 1 : 0;
                    const uint4* mp = mrow_p + nt * 16;
                    mreg[0] = mp[0];
                    mreg[1] = mp[1];
                }
            }
        } else {
            if (it >= 1) {
                const uint32_t phi = abase + (((it - 1) & 1) ? PHI1 : PHI0);
                // MMA tile it-1 from single-buffered B fragments
                #pragma unroll
                for (int kk = 0; kk < 4; kk++) {
                    uint32_t ah[4];
                    ldsm_x4(ah, phi + a_base + kk * 32);
                    mma16816(acc[0], ah, &bf[kk * 2].x);
                    mma16816(acc[1], ah, &bf[kk * 2 + 1].x);
                }
                // prefetch B fragments for tile it (consumed next phase; wrap)
                {
                    const int nt = (it < NTILES) ? it : 0;
                    const uint2* bp0 = bgp + (size_t)nt * 1024;  // nt*4 jb-units
                    #pragma unroll
                    for (int kk = 0; kk < 4; kk++) {
                        const uint2* bp = bp0 + (size_t)kk * 256;
                        bf[kk * 2]     = __ldg(bp);
                        bf[kk * 2 + 1] = __ldg(bp + 32);
                    }
                }
            }
        }
    }

    // ---- epilogue ----
    if (w < 8) {
        float zlo, zhi;
        upk2(zlo, zhi, zacc);
        float zsum = zlo + zhi;
        zsum += __shfl_xor_sync(0xffffffffu, zsum, 1);
        zsum += __shfl_xor_sync(0xffffffffu, zsum, 2);
        zsum += __shfl_xor_sync(0xffffffffu, zsum, 4);
        if ((t & 7) == 0) zs[prow] = zsum;
    }
    __syncthreads();
    if (w >= 8) {
        const int r0 = mgrp * 16 + (lane >> 2);
        const float rz0 = 1.0f / zs[r0];
        const float rz1 = 1.0f / zs[r0 + 8];
        #pragma unroll
        for (int nf = 0; nf < 2; nf++) {
            const int col = ngrp * 16 + nf * 8 + (lane & 3) * 2;
            *reinterpret_cast<float2*>(
                out + (size_t)(ibase + r0) * D_OUT + col) =
                make_float2(acc[nf][0] * rz0, acc[nf][1] * rz0);
            *reinterpret_cast<float2*>(
                out + (size_t)(ibase + r0 + 8) * D_OUT + col) =
                make_float2(acc[nf][2] * rz1, acc[nf][3] * rz1);
        }
    }
}

// ---------------- launch ----------------
extern "C" void kernel_launch(void* const* d_in, const int* in_sizes, int n_in,
                              void* d_out, int out_size) {
    const float* x     = (const float*)d_in[0];   // [8192, 256]
    const int*   mask  = (const int*)d_in[1];     // [8192, 8192]
    const float* trans = (const float*)d_in[2];   // [256, 64]
    const float* attn  = (const float*)d_in[3];   // [128, 1]
    float* out = (float*)d_out;                   // [8192, 64]

    cudaFuncSetAttribute(k_attn_ws, cudaFuncAttributeMaxDynamicSharedMemorySize,
                         SMEM_BYTES);

    k_h_gemm<<<N_NODES / 16, 256>>>(x, trans);
    k_e<<<N_NODES / 8, 256>>>(attn);

    float* e2g;
    cudaGetSymbolAddress((void**)&e2g, g_e2);
    k_attn_ws<<<N_NODES / ROWS, 512, SMEM_BYTES>>>(mask, e2g, out);
}